// round 3
// baseline (speedup 1.0000x reference)
#include <cuda_runtime.h>
#include <math.h>

#define M_LV 4096
#define HID 256
#define PP 16
#define NLEV 16
#define NTOT (NLEV * M_LV)
#define OUTW 1024
#define LN_EPS 1e-5f

// Scratch (per-level working set). Device globals: no allocation allowed.
__device__ float g_K[M_LV * HID];
__device__ float g_V[M_LV * HID];
__device__ float g_Q[M_LV * HID];
__device__ float g_A[M_LV * HID];
__device__ float g_T[M_LV * HID];
__device__ float g_Z[M_LV * HID];

// ---------------------------------------------------------------------------
// GEMM: C[M,N] = A[M,K] @ B[N,K]^T (+ bias[N]) (+= C)   with K = 256 fixed.
// BM=64, BN=64, BK=16, 256 threads, 4x4 microtile per thread.
// ---------------------------------------------------------------------------
template <bool ACCUM, bool BIAS>
__global__ void __launch_bounds__(256)
gemm_nt(const float* __restrict__ A, int lda,
        const float* __restrict__ B, int ldb,
        const float* __restrict__ bias,
        float* __restrict__ C, int ldc) {
    const int BK = 16;
    const int KD = 256;
    __shared__ float As[16][64];
    __shared__ float Bs[16][64];

    int tid = threadIdx.x;
    int tx = tid & 15;        // 0..15 -> output cols tx*4..tx*4+3
    int ty = tid >> 4;        // 0..15 -> output rows ty*4..ty*4+3
    long m0 = (long)blockIdx.x * 64;
    int n0 = blockIdx.y * 64;

    int lrow = tid >> 2;          // 0..63
    int lcol = (tid & 3) << 2;    // 0,4,8,12

    float acc[4][4];
#pragma unroll
    for (int i = 0; i < 4; i++)
#pragma unroll
        for (int j = 0; j < 4; j++) acc[i][j] = 0.0f;

    for (int k0 = 0; k0 < KD; k0 += BK) {
        float4 av = *(const float4*)(A + (m0 + lrow) * (long)lda + k0 + lcol);
        float4 bv = *(const float4*)(B + (long)(n0 + lrow) * ldb + k0 + lcol);
        As[lcol + 0][lrow] = av.x;
        As[lcol + 1][lrow] = av.y;
        As[lcol + 2][lrow] = av.z;
        As[lcol + 3][lrow] = av.w;
        Bs[lcol + 0][lrow] = bv.x;
        Bs[lcol + 1][lrow] = bv.y;
        Bs[lcol + 2][lrow] = bv.z;
        Bs[lcol + 3][lrow] = bv.w;
        __syncthreads();
#pragma unroll
        for (int kk = 0; kk < BK; kk++) {
            float4 a = *(const float4*)&As[kk][ty * 4];
            float4 b = *(const float4*)&Bs[kk][tx * 4];
            float ar[4] = {a.x, a.y, a.z, a.w};
            float br[4] = {b.x, b.y, b.z, b.w};
#pragma unroll
            for (int i = 0; i < 4; i++)
#pragma unroll
                for (int j = 0; j < 4; j++) acc[i][j] += ar[i] * br[j];
        }
        __syncthreads();
    }

#pragma unroll
    for (int i = 0; i < 4; i++) {
        long row = m0 + ty * 4 + i;
#pragma unroll
        for (int j = 0; j < 4; j++) {
            int col = n0 + tx * 4 + j;
            float v = acc[i][j];
            if (BIAS) v += bias[col];
            if (ACCUM) v += C[row * (long)ldc + col];
            C[row * (long)ldc + col] = v;
        }
    }
}

// ---------------------------------------------------------------------------
// Attention: one warp per node. qh from g_Q, K/V gathered by preds from
// per-level scratch. 4 heads of 64 dims; lane owns 8 dims (head = lane/8).
// ---------------------------------------------------------------------------
__global__ void __launch_bounds__(128)
attn_kernel(const float* __restrict__ Q, const float* __restrict__ K,
            const float* __restrict__ V, const int* __restrict__ preds,
            int predBase, float* __restrict__ Agg) {
    int warp = threadIdx.x >> 5;
    int lane = threadIdx.x & 31;
    int m = blockIdx.x * 4 + warp;

    const float scale = 0.125f;  // 1/sqrt(64)
    const float* qp = Q + (long)m * HID + lane * 8;
    float4 q0 = *(const float4*)qp;
    float4 q1 = *(const float4*)(qp + 4);

    int pidx_own = 0;
    if (lane < PP) pidx_own = preds[(long)m * PP + lane] - predBase;

    float s[PP];
#pragma unroll
    for (int p = 0; p < PP; p++) {
        int pi = __shfl_sync(0xffffffffu, pidx_own, p);
        const float* kp = K + (long)pi * HID + lane * 8;
        float4 k0 = *(const float4*)kp;
        float4 k1 = *(const float4*)(kp + 4);
        float d = q0.x * k0.x + q0.y * k0.y + q0.z * k0.z + q0.w * k0.w +
                  q1.x * k1.x + q1.y * k1.y + q1.z * k1.z + q1.w * k1.w;
        // reduce over the 8 lanes of this head
        d += __shfl_xor_sync(0xffffffffu, d, 1);
        d += __shfl_xor_sync(0xffffffffu, d, 2);
        d += __shfl_xor_sync(0xffffffffu, d, 4);
        s[p] = d * scale;
    }

    float mx = s[0];
#pragma unroll
    for (int p = 1; p < PP; p++) mx = fmaxf(mx, s[p]);
    float sum = 0.0f;
#pragma unroll
    for (int p = 0; p < PP; p++) {
        s[p] = __expf(s[p] - mx);
        sum += s[p];
    }
    float inv = 1.0f / sum;

    float4 a0 = {0, 0, 0, 0}, a1 = {0, 0, 0, 0};
#pragma unroll
    for (int p = 0; p < PP; p++) {
        int pi = __shfl_sync(0xffffffffu, pidx_own, p);
        float w = s[p] * inv;
        const float* vp = V + (long)pi * HID + lane * 8;
        float4 v0 = *(const float4*)vp;
        float4 v1 = *(const float4*)(vp + 4);
        a0.x += w * v0.x; a0.y += w * v0.y; a0.z += w * v0.z; a0.w += w * v0.w;
        a1.x += w * v1.x; a1.y += w * v1.y; a1.z += w * v1.z; a1.w += w * v1.w;
    }
    float* op = Agg + (long)m * HID + lane * 8;
    *(float4*)op = a0;
    *(float4*)(op + 4) = a1;
}

// ---------------------------------------------------------------------------
// LayerNorm + exact GELU. One warp per row (256 elems, 8 per lane).
// ---------------------------------------------------------------------------
__global__ void __launch_bounds__(256)
ln_gelu_kernel(const float* __restrict__ Z, const float* __restrict__ g,
               const float* __restrict__ b, float* __restrict__ outp, int ldout) {
    int warp = threadIdx.x >> 5;
    int lane = threadIdx.x & 31;
    int row = blockIdx.x * 8 + warp;

    const float* zp = Z + (long)row * HID + lane * 8;
    float v[8];
    float4 z0 = *(const float4*)zp;
    float4 z1 = *(const float4*)(zp + 4);
    v[0] = z0.x; v[1] = z0.y; v[2] = z0.z; v[3] = z0.w;
    v[4] = z1.x; v[5] = z1.y; v[6] = z1.z; v[7] = z1.w;

    float sum = 0.0f, sq = 0.0f;
#pragma unroll
    for (int j = 0; j < 8; j++) {
        sum += v[j];
        sq += v[j] * v[j];
    }
#pragma unroll
    for (int off = 16; off >= 1; off >>= 1) {
        sum += __shfl_xor_sync(0xffffffffu, sum, off);
        sq += __shfl_xor_sync(0xffffffffu, sq, off);
    }
    float mean = sum * (1.0f / HID);
    float var = sq * (1.0f / HID) - mean * mean;
    float rstd = rsqrtf(var + LN_EPS);

    float o[8];
#pragma unroll
    for (int j = 0; j < 8; j++) {
        int c = lane * 8 + j;
        float y = (v[j] - mean) * rstd * g[c] + b[c];
        o[j] = 0.5f * y * (1.0f + erff(y * 0.70710678118654752f));
    }
    float* op = outp + (long)row * ldout + lane * 8;
    *(float4*)op = make_float4(o[0], o[1], o[2], o[3]);
    *(float4*)(op + 4) = make_float4(o[4], o[5], o[6], o[7]);
}

// Copy level-0 rows (sources are never updated) from slice l to slice l+1.
__global__ void __launch_bounds__(256)
copy_lvl0(float* __restrict__ outp, int l) {
    int row = blockIdx.x;
    int c = threadIdx.x;
    outp[(long)row * OUTW + (l + 1) * HID + c] = outp[(long)row * OUTW + l * HID + c];
}

// ---------------------------------------------------------------------------
extern "C" void kernel_launch(void* const* d_in, const int* in_sizes, int n_in,
                              void* d_out, int out_size) {
    const float* x    = (const float*)d_in[0];
    // d_in[1] = edge_index (int64) unused; d_in[2] = nodes_lv unused (contiguous ranges)
    const int*   preds = (const int*)d_in[3];
    const float* W_in = (const float*)d_in[4];
    const float* b_in = (const float*)d_in[5];
    const float* Wq = (const float*)d_in[6],  *bq = (const float*)d_in[7];
    const float* Wk = (const float*)d_in[8],  *bk = (const float*)d_in[9];
    const float* Wv = (const float*)d_in[10], *bv = (const float*)d_in[11];
    const float* Wo = (const float*)d_in[12], *bo = (const float*)d_in[13];
    const float* Wc = (const float*)d_in[14], *bc = (const float*)d_in[15];
    const float* lg = (const float*)d_in[16], *lb = (const float*)d_in[17];
    float* outp = (float*)d_out;

    float *K_, *V_, *Q_, *A_, *T_, *Z_;
    cudaGetSymbolAddress((void**)&K_, g_K);
    cudaGetSymbolAddress((void**)&V_, g_V);
    cudaGetSymbolAddress((void**)&Q_, g_Q);
    cudaGetSymbolAddress((void**)&A_, g_A);
    cudaGetSymbolAddress((void**)&T_, g_T);
    cudaGetSymbolAddress((void**)&Z_, g_Z);

    dim3 blk(256);
    dim3 gIn(NTOT / 64, 4);
    dim3 gLv(M_LV / 64, 4);

    // Input projection: h0 = x @ W_in^T + b_in -> out columns [0,256)
    gemm_nt<false, true><<<gIn, blk>>>(x, HID, W_in, HID, b_in, outp, OUTW);

    for (int l = 0; l < 3; l++) {
        const float* prev = outp + l * HID;        // previous layer state slice
        float* cur = outp + (l + 1) * HID;         // this layer's state slice
        const float* Wq_l = Wq + (long)l * HID * HID;
        const float* Wk_l = Wk + (long)l * HID * HID;
        const float* Wv_l = Wv + (long)l * HID * HID;
        const float* Wo_l = Wo + (long)l * HID * HID;
        const float* Wc_l = Wc + (long)l * HID * 2 * HID;
        const float* bq_l = bq + l * HID;
        const float* bk_l = bk + l * HID;
        const float* bv_l = bv + l * HID;
        const float* bo_l = bo + l * HID;
        const float* bc_l = bc + l * HID;
        const float* lg_l = lg + l * HID;
        const float* lb_l = lb + l * HID;

        copy_lvl0<<<M_LV, 256>>>(outp, l);

        for (int s = 0; s < NLEV - 1; s++) {
            size_t rlo = (size_t)s * M_LV;        // this level's (already final) rows
            size_t rhi = (size_t)(s + 1) * M_LV;  // rows being computed

            // K/V of level s from current-layer state
            gemm_nt<false, true><<<gLv, blk>>>(cur + rlo * OUTW, OUTW, Wk_l, HID, bk_l, K_, HID);
            gemm_nt<false, true><<<gLv, blk>>>(cur + rlo * OUTW, OUTW, Wv_l, HID, bv_l, V_, HID);
            // Q of level s+1 from previous-layer state
            gemm_nt<false, true><<<gLv, blk>>>(prev + rhi * OUTW, OUTW, Wq_l, HID, bq_l, Q_, HID);
            // Per-head attention over 16 predecessors
            attn_kernel<<<M_LV / 4, 128>>>(Q_, K_, V_, preds + (size_t)s * M_LV * PP,
                                           s * M_LV, A_);
            // Output projection
            gemm_nt<false, true><<<gLv, blk>>>(A_, HID, Wo_l, HID, bo_l, T_, HID);
            // z = [q, agg] @ Wc^T + bc  (two half-K GEMMs into Z_)
            gemm_nt<false, true><<<gLv, blk>>>(prev + rhi * OUTW, OUTW, Wc_l, 2 * HID, bc_l, Z_, HID);
            gemm_nt<true, false><<<gLv, blk>>>(T_, HID, Wc_l + HID, 2 * HID, nullptr, Z_, HID);
            // LayerNorm + GELU -> current layer slice, rows of level s+1
            ln_gelu_kernel<<<M_LV / 8, 256>>>(Z_, lg_l, lb_l, cur + rhi * OUTW, OUTW);
        }
    }
}

// round 5
// speedup vs baseline: 1.4526x; 1.4526x over previous
#include <cuda_runtime.h>
#include <math.h>

#define M_LV 4096
#define HID 256
#define PP 16
#define NLEV 16
#define NTOT (NLEV * M_LV)
#define OUTW 1024
#define LN_EPS 1e-5f
#define LVL1N ((NLEV - 1) * M_LV)   // 61440 rows (levels 1..15)

// ------------------------- device scratch (no allocs) ----------------------
__device__ float g_K[M_LV * HID];
__device__ float g_V[M_LV * HID];
__device__ float g_A[M_LV * HID];
__device__ float g_Z[M_LV * HID];
__device__ float g_Q[LVL1N * HID];       // Q for all levels 1..15 of a layer
__device__ float g_Zpre[LVL1N * HID];    // q-part of z (incl. bias) for levels 1..15
__device__ float g_Wf[3 * HID * HID];    // fused Wc2 @ Wo per layer
__device__ float g_bzc[3 * HID];         // bc + Wc2 @ bo per layer

// ---------------------------------------------------------------------------
// GEMM (K=256): C[M,N] = A[M,K] @ B[N,K]^T (+bias) (+Cin).
// 64x64 tile, BK=16, 256 threads, 4x4 microtile, double-buffered smem.
// DUAL: second half of blockIdx.y uses B1/bias1/C1 (fused K/V projection).
// ---------------------------------------------------------------------------
template <bool DUAL>
__global__ void __launch_bounds__(256)
gemm_k256(const float* __restrict__ A, int lda,
          const float* __restrict__ B0, const float* __restrict__ B1, int ldb,
          const float* __restrict__ bias0, const float* __restrict__ bias1,
          const float* __restrict__ Cin,
          float* __restrict__ C0, float* __restrict__ C1, int ldc) {
    __shared__ float As[2][16][64];
    __shared__ float Bs[2][16][64];

    int tid = threadIdx.x;
    int tx = tid & 15;
    int ty = tid >> 4;
    long m0 = (long)blockIdx.x * 64;

    const float* B;
    const float* bias;
    float* C;
    int nb = blockIdx.y;
    if (DUAL) {
        int half = gridDim.y >> 1;
        if (nb >= half) { B = B1; bias = bias1; C = C1; nb -= half; }
        else            { B = B0; bias = bias0; C = C0; }
    } else {
        B = B0; bias = bias0; C = C0;
    }
    int n0 = nb * 64;

    int lrow = tid >> 2;          // 0..63
    int lcol = (tid & 3) << 2;    // 0,4,8,12
    const float* Ag = A + (m0 + lrow) * (long)lda + lcol;
    const float* Bg = B + (long)(n0 + lrow) * ldb + lcol;

    float4 av = *(const float4*)Ag;
    float4 bv = *(const float4*)Bg;
    As[0][lcol + 0][lrow] = av.x; As[0][lcol + 1][lrow] = av.y;
    As[0][lcol + 2][lrow] = av.z; As[0][lcol + 3][lrow] = av.w;
    Bs[0][lcol + 0][lrow] = bv.x; Bs[0][lcol + 1][lrow] = bv.y;
    Bs[0][lcol + 2][lrow] = bv.z; Bs[0][lcol + 3][lrow] = bv.w;
    __syncthreads();

    float acc[4][4];
#pragma unroll
    for (int i = 0; i < 4; i++)
#pragma unroll
        for (int j = 0; j < 4; j++) acc[i][j] = 0.0f;

#pragma unroll 4
    for (int k0 = 16; k0 <= 256; k0 += 16) {
        int cur = ((k0 >> 4) & 1) ^ 1;
        float4 na, nb4;
        if (k0 < 256) {
            na = *(const float4*)(Ag + k0);
            nb4 = *(const float4*)(Bg + k0);
        }
#pragma unroll
        for (int kk = 0; kk < 16; kk++) {
            float4 a = *(const float4*)&As[cur][kk][ty * 4];
            float4 b = *(const float4*)&Bs[cur][kk][tx * 4];
            float ar[4] = {a.x, a.y, a.z, a.w};
            float br[4] = {b.x, b.y, b.z, b.w};
#pragma unroll
            for (int i = 0; i < 4; i++)
#pragma unroll
                for (int j = 0; j < 4; j++) acc[i][j] += ar[i] * br[j];
        }
        if (k0 < 256) {
            int nxt = cur ^ 1;
            As[nxt][lcol + 0][lrow] = na.x; As[nxt][lcol + 1][lrow] = na.y;
            As[nxt][lcol + 2][lrow] = na.z; As[nxt][lcol + 3][lrow] = na.w;
            Bs[nxt][lcol + 0][lrow] = nb4.x; Bs[nxt][lcol + 1][lrow] = nb4.y;
            Bs[nxt][lcol + 2][lrow] = nb4.z; Bs[nxt][lcol + 3][lrow] = nb4.w;
        }
        __syncthreads();
    }

#pragma unroll
    for (int i = 0; i < 4; i++) {
        long row = m0 + ty * 4 + i;
        float4 v = make_float4(acc[i][0], acc[i][1], acc[i][2], acc[i][3]);
        if (bias) {
            float4 bb = *(const float4*)&bias[n0 + tx * 4];
            v.x += bb.x; v.y += bb.y; v.z += bb.z; v.w += bb.w;
        }
        if (Cin) {
            float4 cc = *(const float4*)&Cin[row * (long)ldc + n0 + tx * 4];
            v.x += cc.x; v.y += cc.y; v.z += cc.z; v.w += cc.w;
        }
        *(float4*)&C[row * (long)ldc + n0 + tx * 4] = v;
    }
}

// ---------------------------------------------------------------------------
// Small NN GEMM: C[n][m] = sum_k A[n][k] * B[k][m]  (256x256x256, Wf fusion)
// ---------------------------------------------------------------------------
__global__ void __launch_bounds__(256)
gemm_nn64(const float* __restrict__ A, int lda,
          const float* __restrict__ B, int ldb,
          float* __restrict__ C, int ldc) {
    __shared__ float As[16][64];
    __shared__ float Bs[16][64];
    int tid = threadIdx.x;
    int tx = tid & 15;
    int ty = tid >> 4;
    int n0 = blockIdx.x * 64;
    int m0 = blockIdx.y * 64;

    int lrow = tid >> 2;
    int lcol = (tid & 3) << 2;
    int brow = tid >> 4;          // 0..15 -> kk
    int bcol = (tid & 15) << 2;   // 0..60

    float acc[4][4];
#pragma unroll
    for (int i = 0; i < 4; i++)
#pragma unroll
        for (int j = 0; j < 4; j++) acc[i][j] = 0.0f;

    for (int k0 = 0; k0 < 256; k0 += 16) {
        float4 av = *(const float4*)(A + (n0 + lrow) * (long)lda + k0 + lcol);
        float4 bv = *(const float4*)(B + (long)(k0 + brow) * ldb + m0 + bcol);
        As[lcol + 0][lrow] = av.x; As[lcol + 1][lrow] = av.y;
        As[lcol + 2][lrow] = av.z; As[lcol + 3][lrow] = av.w;
        *(float4*)&Bs[brow][bcol] = bv;
        __syncthreads();
#pragma unroll
        for (int kk = 0; kk < 16; kk++) {
            float4 a = *(const float4*)&As[kk][ty * 4];
            float4 b = *(const float4*)&Bs[kk][tx * 4];
            float ar[4] = {a.x, a.y, a.z, a.w};
            float br[4] = {b.x, b.y, b.z, b.w};
#pragma unroll
            for (int i = 0; i < 4; i++)
#pragma unroll
                for (int j = 0; j < 4; j++) acc[i][j] += ar[i] * br[j];
        }
        __syncthreads();
    }
#pragma unroll
    for (int i = 0; i < 4; i++)
#pragma unroll
        for (int j = 0; j < 4; j++)
            C[(long)(n0 + ty * 4 + i) * ldc + m0 + tx * 4 + j] = acc[i][j];
}

// bzc[n] = bc[n] + sum_k Wc2[n][k] * bo[k]
__global__ void make_bzc(const float* __restrict__ Wc_l,
                         const float* __restrict__ bo_l,
                         const float* __restrict__ bc_l,
                         float* __restrict__ bzc) {
    int n = threadIdx.x;
    float s = 0.0f;
    const float* wr = Wc_l + (long)n * 2 * HID + HID;
    for (int k = 0; k < HID; k++) s += wr[k] * bo_l[k];
    bzc[n] = bc_l[n] + s;
}

// ---------------------------------------------------------------------------
// Attention: one warp per node, 4 heads x 64 dims, lane owns 8 dims.
// ---------------------------------------------------------------------------
__global__ void __launch_bounds__(128)
attn_kernel(const float* __restrict__ Q, const float* __restrict__ K,
            const float* __restrict__ V, const int* __restrict__ preds,
            int predBase, float* __restrict__ Agg) {
    int warp = threadIdx.x >> 5;
    int lane = threadIdx.x & 31;
    int m = blockIdx.x * 4 + warp;

    const float scale = 0.125f;  // 1/sqrt(64)
    const float* qp = Q + (long)m * HID + lane * 8;
    float4 q0 = *(const float4*)qp;
    float4 q1 = *(const float4*)(qp + 4);

    int pidx_own = 0;
    if (lane < PP) pidx_own = preds[(long)m * PP + lane] - predBase;

    float s[PP];
#pragma unroll
    for (int p = 0; p < PP; p++) {
        int pi = __shfl_sync(0xffffffffu, pidx_own, p);
        const float* kp = K + (long)pi * HID + lane * 8;
        float4 k0 = *(const float4*)kp;
        float4 k1 = *(const float4*)(kp + 4);
        float d = q0.x * k0.x + q0.y * k0.y + q0.z * k0.z + q0.w * k0.w +
                  q1.x * k1.x + q1.y * k1.y + q1.z * k1.z + q1.w * k1.w;
        d += __shfl_xor_sync(0xffffffffu, d, 1);
        d += __shfl_xor_sync(0xffffffffu, d, 2);
        d += __shfl_xor_sync(0xffffffffu, d, 4);
        s[p] = d * scale;
    }

    float mx = s[0];
#pragma unroll
    for (int p = 1; p < PP; p++) mx = fmaxf(mx, s[p]);
    float sum = 0.0f;
#pragma unroll
    for (int p = 0; p < PP; p++) {
        s[p] = __expf(s[p] - mx);
        sum += s[p];
    }
    float inv = 1.0f / sum;

    float4 a0 = {0, 0, 0, 0}, a1 = {0, 0, 0, 0};
#pragma unroll
    for (int p = 0; p < PP; p++) {
        int pi = __shfl_sync(0xffffffffu, pidx_own, p);
        float w = s[p] * inv;
        const float* vp = V + (long)pi * HID + lane * 8;
        float4 v0 = *(const float4*)vp;
        float4 v1 = *(const float4*)(vp + 4);
        a0.x += w * v0.x; a0.y += w * v0.y; a0.z += w * v0.z; a0.w += w * v0.w;
        a1.x += w * v1.x; a1.y += w * v1.y; a1.z += w * v1.z; a1.w += w * v1.w;
    }
    float* op = Agg + (long)m * HID + lane * 8;
    *(float4*)op = a0;
    *(float4*)(op + 4) = a1;
}

// ---------------------------------------------------------------------------
// LayerNorm + exact GELU. One warp per row.
// ---------------------------------------------------------------------------
__global__ void __launch_bounds__(256)
ln_gelu_kernel(const float* __restrict__ Z, const float* __restrict__ g,
               const float* __restrict__ b, float* __restrict__ outp, int ldout) {
    int warp = threadIdx.x >> 5;
    int lane = threadIdx.x & 31;
    int row = blockIdx.x * 8 + warp;

    const float* zp = Z + (long)row * HID + lane * 8;
    float v[8];
    float4 z0 = *(const float4*)zp;
    float4 z1 = *(const float4*)(zp + 4);
    v[0] = z0.x; v[1] = z0.y; v[2] = z0.z; v[3] = z0.w;
    v[4] = z1.x; v[5] = z1.y; v[6] = z1.z; v[7] = z1.w;

    float sum = 0.0f, sq = 0.0f;
#pragma unroll
    for (int j = 0; j < 8; j++) { sum += v[j]; sq += v[j] * v[j]; }
#pragma unroll
    for (int off = 16; off >= 1; off >>= 1) {
        sum += __shfl_xor_sync(0xffffffffu, sum, off);
        sq += __shfl_xor_sync(0xffffffffu, sq, off);
    }
    float mean = sum * (1.0f / HID);
    float var = sq * (1.0f / HID) - mean * mean;
    float rstd = rsqrtf(var + LN_EPS);

    float o[8];
#pragma unroll
    for (int j = 0; j < 8; j++) {
        int c = lane * 8 + j;
        float y = (v[j] - mean) * rstd * g[c] + b[c];
        o[j] = 0.5f * y * (1.0f + erff(y * 0.70710678118654752f));
    }
    float* op = outp + (long)row * ldout + lane * 8;
    *(float4*)op = make_float4(o[0], o[1], o[2], o[3]);
    *(float4*)(op + 4) = make_float4(o[4], o[5], o[6], o[7]);
}

// Copy level-0 rows from slice l to slice l+1 (sources never updated).
__global__ void __launch_bounds__(256)
copy_lvl0(float* __restrict__ outp, int l) {
    int row = blockIdx.x;
    int c = threadIdx.x;
    outp[(long)row * OUTW + (l + 1) * HID + c] = outp[(long)row * OUTW + l * HID + c];
}

// ---------------------------------------------------------------------------
extern "C" void kernel_launch(void* const* d_in, const int* in_sizes, int n_in,
                              void* d_out, int out_size) {
    const float* x     = (const float*)d_in[0];
    const int*   preds = (const int*)d_in[3];
    const float* W_in  = (const float*)d_in[4];
    const float* b_in  = (const float*)d_in[5];
    const float* Wq = (const float*)d_in[6],  *bq = (const float*)d_in[7];
    const float* Wk = (const float*)d_in[8],  *bk = (const float*)d_in[9];
    const float* Wv = (const float*)d_in[10], *bv = (const float*)d_in[11];
    const float* Wo = (const float*)d_in[12], *bo = (const float*)d_in[13];
    const float* Wc = (const float*)d_in[14], *bc = (const float*)d_in[15];
    const float* lg = (const float*)d_in[16], *lb = (const float*)d_in[17];
    float* outp = (float*)d_out;

    float *K_, *V_, *A_, *Z_, *Q_, *Zpre_, *Wf_, *bzc_;
    cudaGetSymbolAddress((void**)&K_, g_K);
    cudaGetSymbolAddress((void**)&V_, g_V);
    cudaGetSymbolAddress((void**)&A_, g_A);
    cudaGetSymbolAddress((void**)&Z_, g_Z);
    cudaGetSymbolAddress((void**)&Q_, g_Q);
    cudaGetSymbolAddress((void**)&Zpre_, g_Zpre);
    cudaGetSymbolAddress((void**)&Wf_, g_Wf);
    cudaGetSymbolAddress((void**)&bzc_, g_bzc);

    dim3 blk(256);

    // Input projection: h0 = x @ W_in^T + b_in -> out columns [0,256)
    gemm_k256<false><<<dim3(NTOT / 64, 4), blk>>>(
        x, HID, W_in, nullptr, HID, b_in, nullptr, nullptr, outp, nullptr, OUTW);

    for (int l = 0; l < 3; l++) {
        const float* prev = outp + l * HID;
        float* cur = outp + (l + 1) * HID;
        const float* Wq_l = Wq + (long)l * HID * HID;
        const float* Wk_l = Wk + (long)l * HID * HID;
        const float* Wv_l = Wv + (long)l * HID * HID;
        const float* Wo_l = Wo + (long)l * HID * HID;
        const float* Wc_l = Wc + (long)l * HID * 2 * HID;
        const float* bq_l = bq + l * HID;
        const float* bk_l = bk + l * HID;
        const float* bv_l = bv + l * HID;
        const float* bo_l = bo + l * HID;
        const float* bc_l = bc + l * HID;
        const float* lg_l = lg + l * HID;
        const float* lb_l = lb + l * HID;
        float* Wf_l = Wf_ + (long)l * HID * HID;
        float* bzc_l = bzc_ + l * HID;

        // Fold Wo into the agg-half of Wc: Wf = Wc2 @ Wo, bzc = bc + Wc2 @ bo
        gemm_nn64<<<dim3(4, 4), blk>>>(Wc_l + HID, 2 * HID, Wo_l, HID, Wf_l, HID);
        make_bzc<<<1, 256>>>(Wc_l, bo_l, bc_l, bzc_l);

        copy_lvl0<<<M_LV, 256>>>(outp, l);

        // Hoisted off critical path: Q and q-part of z for ALL levels 1..15
        gemm_k256<false><<<dim3(LVL1N / 64, 4), blk>>>(
            prev + (long)M_LV * OUTW, OUTW, Wq_l, nullptr, HID,
            bq_l, nullptr, nullptr, Q_, nullptr, HID);
        gemm_k256<false><<<dim3(LVL1N / 64, 4), blk>>>(
            prev + (long)M_LV * OUTW, OUTW, Wc_l, nullptr, 2 * HID,
            bzc_l, nullptr, nullptr, Zpre_, nullptr, HID);

        for (int s = 0; s < NLEV - 1; s++) {
            size_t rlo = (size_t)s * M_LV;
            size_t rhi = (size_t)(s + 1) * M_LV;
            (void)rhi;

            // Fused K/V projection of level s (dual-output GEMM, 512 blocks)
            gemm_k256<true><<<dim3(M_LV / 64, 8), blk>>>(
                cur + rlo * OUTW, OUTW, Wk_l, Wv_l, HID,
                bk_l, bv_l, nullptr, K_, V_, HID);

            attn_kernel<<<M_LV / 4, 128>>>(
                Q_ + rlo * HID, K_, V_, preds + rlo * PP, s * M_LV, A_);

            // z = Zpre + agg @ Wf^T
            gemm_k256<false><<<dim3(M_LV / 64, 4), blk>>>(
                A_, HID, Wf_l, nullptr, HID,
                nullptr, nullptr, Zpre_ + rlo * HID, Z_, nullptr, HID);

            ln_gelu_kernel<<<M_LV / 8, 256>>>(
                Z_, lg_l, lb_l, cur + (rlo + M_LV) * OUTW, OUTW);
        }
    }
}